// round 7
// baseline (speedup 1.0000x reference)
#include <cuda_runtime.h>
#include <math.h>

#define Bn   16
#define Tn   750
#define Fd   4096
#define Cd   20
#define KS   93
#define NROW (Bn*Tn)          // 12000

// ---- output layout (float elements) ----
#define OFF_SACT 0
#define OFF_SBKG 320
#define OFF_FACT 640
#define OFF_FBKG 6095488
#define OFF_FEAT 12190336
#define OFF_CSM  61342336

// ---- device scratch (no allocations allowed) ----
__device__ float g_cas[NROW*Cd];
__device__ float g_mag[NROW];
__device__ int   g_idx_act[Bn*KS];
__device__ int   g_idx_bkg[Bn*KS];
__device__ float g_sact[Bn*Cd];

// ---- packed f32x2 helpers (Blackwell sm_10x) ----
__device__ __forceinline__ void fma2(unsigned long long& d,
                                     unsigned long long a, unsigned long long b) {
    asm("fma.rn.f32x2 %0, %1, %2, %0;" : "+l"(d) : "l"(a), "l"(b));
}
__device__ __forceinline__ unsigned long long mul2(unsigned long long a,
                                                   unsigned long long b) {
    unsigned long long d;
    asm("mul.rn.f32x2 %0, %1, %2;" : "=l"(d) : "l"(a), "l"(b));
    return d;
}
__device__ __forceinline__ float hadd2(unsigned long long v) {
    return __uint_as_float((unsigned)v) + __uint_as_float((unsigned)(v >> 32));
}
__device__ __forceinline__ double hadd2d(unsigned long long v) {
    return (double)__uint_as_float((unsigned)v) +
           (double)__uint_as_float((unsigned)(v >> 32));
}

// ============================================================================
// K1: fused per-row pass. 750 blocks x 512 threads, 16 rows/block.
// Layout: 4 row-groups (4 rows each) x 4 warps; each warp covers 5 classes
// over the FULL feature range -> acc[5][4] b64 (40 regs), warp-local cas
// reduction. All math via packed f32x2 (2 FMAs / instruction).
// smem: W chunk (20 x 256 ulonglong2 = 81920B) + cass (1280B)
// ============================================================================
__global__ __launch_bounds__(512, 1) void k1_main(
    const ulonglong2* __restrict__ xg, const ulonglong2* __restrict__ Wg,
    const ulonglong2* __restrict__ mg, ulonglong2* __restrict__ featg,
    float* __restrict__ cas_sm)
{
    extern __shared__ char smraw[];
    ulonglong2* smw  = (ulonglong2*)smraw;            // [Cd*256]
    float*      cass = (float*)(smraw + 81920);       // [16][Cd]

    const int tid  = threadIdx.x;
    const int lane = tid & 31;
    const int warp = tid >> 5;
    const int rg   = warp >> 2;         // row-group 0..3
    const int cw   = warp & 3;          // class-warp 0..3 -> classes cw*5..cw*5+4
    const int row0 = blockIdx.x * 16 + rg * 4;
    const int cbase = cw * 5;

    unsigned long long acc[5][4];
    #pragma unroll
    for (int c = 0; c < 5; c++)
        #pragma unroll
        for (int r = 0; r < 4; r++) acc[c][r] = 0ull;
    unsigned long long ssq[4] = {0ull, 0ull, 0ull, 0ull};

    for (int ch = 0; ch < 4; ch++) {
        __syncthreads();
        // cooperative W chunk load: Cd x 256 ulonglong2
        for (int k = tid; k < Cd * 256; k += 512) {
            int c = k >> 8, p = k & 255;
            smw[k] = __ldg(&Wg[c * 1024 + ch * 256 + p]);
        }
        __syncthreads();

        #pragma unroll 2
        for (int it = 0; it < 8; it++) {
            const int fi = ch * 256 + it * 32 + lane;   // float4 index in row
            unsigned long long xlo[4], xhi[4];
            #pragma unroll
            for (int r = 0; r < 4; r++) {
                const int a = (row0 + r) * 1024 + fi;
                ulonglong2 xv = __ldg(&xg[a]);
                ulonglong2 mv = __ldg(&mg[a]);
                if (cw == 0) {
                    featg[a] = xv;
                    fma2(ssq[r], xv.x, xv.x);
                    fma2(ssq[r], xv.y, xv.y);
                }
                xlo[r] = mul2(xv.x, mv.x);
                xhi[r] = mul2(xv.y, mv.y);
            }
            const int sb = it * 32 + lane;
            #pragma unroll
            for (int c = 0; c < 5; c++) {
                ulonglong2 wv = smw[(cbase + c) * 256 + sb];
                #pragma unroll
                for (int r = 0; r < 4; r++) fma2(acc[c][r], wv.x, xlo[r]);
                #pragma unroll
                for (int r = 0; r < 4; r++) fma2(acc[c][r], wv.y, xhi[r]);
            }
        }
    }

    // ---- warp-local cas reduction ----
    #pragma unroll
    for (int c = 0; c < 5; c++) {
        #pragma unroll
        for (int r = 0; r < 4; r++) {
            float s = hadd2(acc[c][r]);
            s += __shfl_down_sync(0xffffffffu, s, 16);
            s += __shfl_down_sync(0xffffffffu, s, 8);
            s += __shfl_down_sync(0xffffffffu, s, 4);
            s += __shfl_down_sync(0xffffffffu, s, 2);
            s += __shfl_down_sync(0xffffffffu, s, 1);
            if (lane == 0) {
                int cc = cbase + c;
                cass[(rg * 4 + r) * Cd + cc] = s;
                g_cas[(row0 + r) * Cd + cc]  = s;
            }
        }
    }
    // ---- mag (fp64 cross-lane) ----
    if (cw == 0) {
        #pragma unroll
        for (int r = 0; r < 4; r++) {
            double d = hadd2d(ssq[r]);
            d += __shfl_down_sync(0xffffffffu, d, 16);
            d += __shfl_down_sync(0xffffffffu, d, 8);
            d += __shfl_down_sync(0xffffffffu, d, 4);
            d += __shfl_down_sync(0xffffffffu, d, 2);
            d += __shfl_down_sync(0xffffffffu, d, 1);
            if (lane == 0) g_mag[row0 + r] = (float)sqrt(d);
        }
    }
    __syncthreads();

    // ---- cas softmax over classes, one thread per row ----
    if (tid < 16) {
        int row = blockIdx.x * 16 + tid;
        float m = -1e30f;
        #pragma unroll
        for (int c = 0; c < Cd; c++) m = fmaxf(m, cass[tid * Cd + c]);
        float e[Cd]; float s = 0.f;
        #pragma unroll
        for (int c = 0; c < Cd; c++) { e[c] = expf(cass[tid * Cd + c] - m); s += e[c]; }
        float inv = 1.f / s;
        #pragma unroll
        for (int c = 0; c < Cd; c++) cas_sm[row * Cd + c] = e[c] * inv;
    }
}

// ============================================================================
// K23: merged top-k kernels. grid 136 x 256 threads.
//  blocks [0,96): K2 — per-batch ordered top-93 indices (rank counting,
//                 stable, matches jax.lax.top_k tie-break).
//  blocks [96,136): K3 — warp-per-(b,c) radix select: exact sum of top-93
//                 cas values with tie compensation. No block barriers.
// ============================================================================
__global__ void k23(const float* __restrict__ sel)
{
    __shared__ float sh[12000];   // 48000B, shared by both paths
    __shared__ float wmax[8];
    const int tid = threadIdx.x;

    if (blockIdx.x < 96) {
        // ---------------- K2 ----------------
        const int b = blockIdx.x / 6, chunk = blockIdx.x % 6;
        float* md  = sh;
        float* mrd = sh + Tn;

        float lmax = -1e30f;
        for (int i = tid; i < Tn; i += 256) {
            float m = g_mag[b * Tn + i];
            float s = sel[b * Tn + i];
            md[i] = m; mrd[i] = s;
            lmax = fmaxf(lmax, m);
        }
        for (int o = 16; o > 0; o >>= 1)
            lmax = fmaxf(lmax, __shfl_down_sync(0xffffffffu, lmax, o));
        if ((tid & 31) == 0) wmax[tid >> 5] = lmax;
        __syncthreads();
        float maxm = wmax[0];
        #pragma unroll
        for (int w = 1; w < 8; w++) maxm = fmaxf(maxm, wmax[w]);
        for (int i = tid; i < Tn; i += 256) {
            float m = md[i], s = mrd[i];
            md[i]  = m * s;
            mrd[i] = (maxm - m) * s;
        }
        __syncthreads();

        const int i = chunk * 125 + tid;
        if (tid < 125) {
            float v1 = md[i], v2 = mrd[i];
            int r1 = 0, r2 = 0;
            #pragma unroll 5
            for (int j = 0; j < Tn; j++) {
                float u1 = md[j];
                r1 += (int)(u1 > v1) + (int)((u1 == v1) & (j < i));
                float u2 = mrd[j];
                r2 += (int)(u2 > v2) + (int)((u2 == v2) & (j < i));
            }
            if (r1 < KS) g_idx_act[b * KS + r1] = i;
            if (r2 < KS) g_idx_bkg[b * KS + r2] = i;
        }
    } else {
        // ---------------- K3: warp per (b,c) ----------------
        const int w = tid >> 5, lane = tid & 31;
        const int pair = (blockIdx.x - 96) * 8 + w;   // 0..319
        const int b = pair / Cd, c = pair % Cd;
        unsigned* key = (unsigned*)(sh + w * 1500);
        float*    col = sh + w * 1500 + Tn;

        for (int i = lane; i < Tn; i += 32) {
            float v = g_cas[(b * Tn + i) * Cd + c];
            col[i] = v;
            unsigned u = __float_as_uint(v);
            key[i] = (u & 0x80000000u) ? ~u : (u | 0x80000000u);
        }
        __syncwarp();

        unsigned prefix = 0u;
        for (int bit = 31; bit >= 0; --bit) {
            unsigned cand = prefix | (1u << bit);
            int cnt = 0;
            for (int i = lane; i < Tn; i += 32) cnt += (int)(key[i] >= cand);
            cnt = (int)__reduce_add_sync(0xffffffffu, (unsigned)cnt);
            if (cnt >= KS) prefix = cand;
        }
        float thr;
        { unsigned u = prefix; u = (u & 0x80000000u) ? (u & 0x7fffffffu) : ~u;
          thr = __uint_as_float(u); }

        int cg = 0; float s = 0.f;
        for (int i = lane; i < Tn; i += 32)
            if (key[i] > prefix) { cg++; s += col[i]; }
        cg = (int)__reduce_add_sync(0xffffffffu, (unsigned)cg);
        for (int o = 16; o > 0; o >>= 1) s += __shfl_down_sync(0xffffffffu, s, o);
        if (lane == 0)
            g_sact[b * Cd + c] = (s + (float)(KS - cg) * thr) * (1.f / (float)KS);
    }
}

// ============================================================================
// K45: merged tail. grid 2992 x 256 threads.
//  blocks [0,2976): K5 gather of feat_act / feat_bkg rows
//  blocks [2976,2992): K4 score_bkg mean + both score softmaxes
// ============================================================================
__global__ void k45(const float4* __restrict__ x4, float* __restrict__ out)
{
    __shared__ float red[12 * Cd];
    __shared__ float sb[Cd], sa[Cd], eb[Cd], ea[Cd];
    const int tid = threadIdx.x;

    if (blockIdx.x < 2976) {
        int idx = blockIdx.x;
        int z = (idx >= 1488) ? 1 : 0;
        idx -= z * 1488;
        const int b = idx / KS, k = idx % KS;
        const int* I = z ? g_idx_bkg : g_idx_act;
        const int t = I[b * KS + k];
        const float4* s = x4 + (long)(b * Tn + t) * 1024;
        float4* d = (float4*)out + (z ? (OFF_FBKG / 4) : (OFF_FACT / 4))
                    + (long)(b * KS + k) * 1024;
        for (int i = tid; i < 1024; i += 256) d[i] = s[i];
    } else {
        const int b = blockIdx.x - 2976;
        float* score_act = out + OFF_SACT;
        float* score_bkg = out + OFF_SBKG;

        if (tid < 240) {
            int c = tid % Cd, p = tid / Cd;
            float s = 0.f;
            for (int k = p; k < KS; k += 12) {
                int t = g_idx_bkg[b * KS + k];
                s += g_cas[(b * Tn + t) * Cd + c];
            }
            red[p * Cd + c] = s;
        }
        __syncthreads();
        if (tid < Cd) {
            float s = 0.f;
            #pragma unroll
            for (int p = 0; p < 12; p++) s += red[p * Cd + tid];
            sb[tid] = s * (1.f / (float)KS);
            sa[tid] = g_sact[b * Cd + tid];
        }
        __syncthreads();
        if (tid < Cd) {
            float mb = -1e30f, ma = -1e30f;
            #pragma unroll
            for (int j = 0; j < Cd; j++) { mb = fmaxf(mb, sb[j]); ma = fmaxf(ma, sa[j]); }
            eb[tid] = expf(sb[tid] - mb);
            ea[tid] = expf(sa[tid] - ma);
        }
        __syncthreads();
        if (tid < Cd) {
            float Sb = 0.f, Sa = 0.f;
            #pragma unroll
            for (int j = 0; j < Cd; j++) { Sb += eb[j]; Sa += ea[j]; }
            score_bkg[b * Cd + tid] = eb[tid] / Sb;
            score_act[b * Cd + tid] = ea[tid] / Sa;
        }
    }
}

// ============================================================================
extern "C" void kernel_launch(void* const* d_in, const int* in_sizes, int n_in,
                              void* d_out, int out_size)
{
    const float* x    = (const float*)d_in[0];
    const float* W    = (const float*)d_in[1];
    const float* mask = (const float*)d_in[2];
    const float* sel  = (const float*)d_in[3];
    float* out = (float*)d_out;

    cudaFuncSetAttribute(k1_main, cudaFuncAttributeMaxDynamicSharedMemorySize, 83200);

    k1_main<<<NROW / 16, 512, 83200>>>(
        (const ulonglong2*)x, (const ulonglong2*)W, (const ulonglong2*)mask,
        (ulonglong2*)(out + OFF_FEAT), out + OFF_CSM);
    k23<<<136, 256>>>(sel);
    k45<<<2992, 256>>>((const float4*)x, out);
}

// round 8
// speedup vs baseline: 1.3232x; 1.3232x over previous
#include <cuda_runtime.h>
#include <math.h>

#define Bn   16
#define Tn   750
#define Fd   4096
#define Cd   20
#define KS   93
#define NROW (Bn*Tn)          // 12000

// ---- output layout (float elements) ----
#define OFF_SACT 0
#define OFF_SBKG 320
#define OFF_FACT 640
#define OFF_FBKG 6095488
#define OFF_FEAT 12190336
#define OFF_CSM  61342336

// ---- device scratch ----
__device__ float g_cas[NROW*Cd];
__device__ float g_mag[NROW];
__device__ int   g_idx_act[Bn*KS];
__device__ int   g_idx_bkg[Bn*KS];
__device__ float g_sact[Bn*Cd];

// ---- packed f32x2 helpers ----
__device__ __forceinline__ void fma2(unsigned long long& d,
                                     unsigned long long a, unsigned long long b) {
    asm("fma.rn.f32x2 %0, %1, %2, %0;" : "+l"(d) : "l"(a), "l"(b));
}
__device__ __forceinline__ unsigned long long mul2(unsigned long long a,
                                                   unsigned long long b) {
    unsigned long long d;
    asm("mul.rn.f32x2 %0, %1, %2;" : "=l"(d) : "l"(a), "l"(b));
    return d;
}
__device__ __forceinline__ float hadd2(unsigned long long v) {
    return __uint_as_float((unsigned)v) + __uint_as_float((unsigned)(v >> 32));
}
__device__ __forceinline__ double hadd2d(unsigned long long v) {
    return (double)__uint_as_float((unsigned)v) +
           (double)__uint_as_float((unsigned)(v >> 32));
}

// ---- cp.async helpers ----
__device__ __forceinline__ unsigned smem_u32(const void* p) {
    return (unsigned)__cvta_generic_to_shared(p);
}
__device__ __forceinline__ void cp16(unsigned dst, const void* src) {
    asm volatile("cp.async.cg.shared.global [%0], [%1], 16;"
                 :: "r"(dst), "l"(src) : "memory");
}
#define CP_COMMIT() asm volatile("cp.async.commit_group;" ::: "memory")
#define CP_WAIT(n)  asm volatile("cp.async.wait_group %0;" :: "n"(n) : "memory")

// ============================================================================
// K1: fused per-row pass, cp.async-pipelined.
// 750 blocks x 512 threads, 16 rows/block.
// Stage ring: 4 stages x (16 rows x 32 f4) for x and mask (64KB).
// Compute: 4 row-groups x 4 class-warps, acc[5][4] f32x2 (round-6 math).
// W staged per 256-f4 chunk in smem (80KB). cass 1.28KB. Total 148736B.
// ============================================================================
#define SM_OFF_W    0
#define SM_OFF_XS   81920
#define SM_OFF_MS   114688
#define SM_OFF_CASS 147456
#define SM_TOTAL    148736

__global__ __launch_bounds__(512, 1) void k1_main(
    const ulonglong2* __restrict__ xg, const ulonglong2* __restrict__ Wg,
    const ulonglong2* __restrict__ mg, ulonglong2* __restrict__ featg,
    float* __restrict__ cas_sm)
{
    extern __shared__ char sm[];
    ulonglong2* smw  = (ulonglong2*)(sm + SM_OFF_W);     // [Cd][256]
    ulonglong2* xs   = (ulonglong2*)(sm + SM_OFF_XS);    // [4][16][32]
    ulonglong2* msb  = (ulonglong2*)(sm + SM_OFF_MS);    // [4][16][32]
    float*      cass = (float*)(sm + SM_OFF_CASS);       // [16][Cd]

    const int tid  = threadIdx.x;
    const int lane = tid & 31;
    const int warp = tid >> 5;
    const int rg   = warp >> 2;          // row-group 0..3
    const int cw   = warp & 3;           // class-warp 0..3
    const int cbase = cw * 5;
    const int row0blk = blockIdx.x * 16;

    // producer mapping: each thread owns (row prow, f4-pos pf) in every stage
    const int prow = tid >> 5;           // 0..15
    const int pf   = tid & 31;           // 0..31
    const ulonglong2* xsrc = xg + (size_t)(row0blk + prow) * 1024 + pf;
    const ulonglong2* msrc = mg + (size_t)(row0blk + prow) * 1024 + pf;
    const unsigned xs_u32 = smem_u32(xs) + (unsigned)(prow * 32 + pf) * 16u;
    const unsigned ms_u32 = smem_u32(msb) + (unsigned)(prow * 32 + pf) * 16u;

    unsigned long long acc[5][4];
    #pragma unroll
    for (int c = 0; c < 5; c++)
        #pragma unroll
        for (int r = 0; r < 4; r++) acc[c][r] = 0ull;
    unsigned long long ssq[4] = {0ull, 0ull, 0ull, 0ull};

    // ---- pipeline prologue: stages 0..2 ----
    #pragma unroll
    for (int s = 0; s < 3; s++) {
        unsigned so = (unsigned)(s & 3) * 8192u;   // 512 ull2 * 16B
        cp16(xs_u32 + so, xsrc + s * 32);
        cp16(ms_u32 + so, msrc + s * 32);
        CP_COMMIT();
    }

    #define COMPUTE_SUB(s)                                                     \
    {                                                                          \
        const int stg = (s) & 3;                                               \
        const int wb  = ((s) & 7) * 32;                                        \
        unsigned long long xlo[4], xhi[4];                                     \
        _Pragma("unroll")                                                      \
        for (int r = 0; r < 4; r++) {                                          \
            const int lrow = rg * 4 + r;                                       \
            ulonglong2 xv = xs[stg * 512 + lrow * 32 + lane];                  \
            ulonglong2 mv = msb[stg * 512 + lrow * 32 + lane];                 \
            if (cw == 0) {                                                     \
                featg[(size_t)(row0blk + lrow) * 1024 + (s) * 32 + lane] = xv; \
                fma2(ssq[r], xv.x, xv.x);                                      \
                fma2(ssq[r], xv.y, xv.y);                                      \
            }                                                                  \
            xlo[r] = mul2(xv.x, mv.x);                                         \
            xhi[r] = mul2(xv.y, mv.y);                                         \
        }                                                                      \
        _Pragma("unroll")                                                      \
        for (int c = 0; c < 5; c++) {                                          \
            ulonglong2 wv = smw[(cbase + c) * 256 + wb + lane];                \
            _Pragma("unroll")                                                  \
            for (int r = 0; r < 4; r++) fma2(acc[c][r], wv.x, xlo[r]);         \
            _Pragma("unroll")                                                  \
            for (int r = 0; r < 4; r++) fma2(acc[c][r], wv.y, xhi[r]);         \
        }                                                                      \
    }

    // ---- main loop over 32 sub-chunks ----
    for (int s = 0; s < 30; s++) {
        if ((s & 7) == 0) {              // new W chunk every 8 sub-chunks
            __syncthreads();
            const int ch = s >> 3;
            for (int k = tid; k < Cd * 256; k += 512)
                smw[k] = __ldg(&Wg[(k >> 8) * 1024 + ch * 256 + (k & 255)]);
            __syncthreads();
        }
        CP_WAIT(2);
        __syncthreads();
        if (s + 3 < 32) {
            unsigned so = (unsigned)((s + 3) & 3) * 8192u;
            cp16(xs_u32 + so, xsrc + (s + 3) * 32);
            cp16(ms_u32 + so, msrc + (s + 3) * 32);
            CP_COMMIT();
        }
        COMPUTE_SUB(s);
    }
    CP_WAIT(1); __syncthreads(); COMPUTE_SUB(30);
    CP_WAIT(0); __syncthreads(); COMPUTE_SUB(31);

    // ---- warp-local cas reduction ----
    #pragma unroll
    for (int c = 0; c < 5; c++) {
        #pragma unroll
        for (int r = 0; r < 4; r++) {
            float s2 = hadd2(acc[c][r]);
            s2 += __shfl_down_sync(0xffffffffu, s2, 16);
            s2 += __shfl_down_sync(0xffffffffu, s2, 8);
            s2 += __shfl_down_sync(0xffffffffu, s2, 4);
            s2 += __shfl_down_sync(0xffffffffu, s2, 2);
            s2 += __shfl_down_sync(0xffffffffu, s2, 1);
            if (lane == 0) {
                int cc = cbase + c;
                cass[(rg * 4 + r) * Cd + cc] = s2;
                g_cas[(row0blk + rg * 4 + r) * Cd + cc] = s2;
            }
        }
    }
    // ---- mag (fp64 cross-lane) ----
    if (cw == 0) {
        #pragma unroll
        for (int r = 0; r < 4; r++) {
            double d = hadd2d(ssq[r]);
            d += __shfl_down_sync(0xffffffffu, d, 16);
            d += __shfl_down_sync(0xffffffffu, d, 8);
            d += __shfl_down_sync(0xffffffffu, d, 4);
            d += __shfl_down_sync(0xffffffffu, d, 2);
            d += __shfl_down_sync(0xffffffffu, d, 1);
            if (lane == 0) g_mag[row0blk + rg * 4 + r] = (float)sqrt(d);
        }
    }
    __syncthreads();

    // ---- cas softmax over classes, one thread per row ----
    if (tid < 16) {
        int row = row0blk + tid;
        float m = -1e30f;
        #pragma unroll
        for (int c = 0; c < Cd; c++) m = fmaxf(m, cass[tid * Cd + c]);
        float e[Cd]; float s = 0.f;
        #pragma unroll
        for (int c = 0; c < Cd; c++) { e[c] = expf(cass[tid * Cd + c] - m); s += e[c]; }
        float inv = 1.f / s;
        #pragma unroll
        for (int c = 0; c < Cd; c++) cas_sm[row * Cd + c] = e[c] * inv;
    }
}

// ============================================================================
// K23: merged top-k kernels. grid 136 x 256 threads.
// ============================================================================
__global__ void k23(const float* __restrict__ sel)
{
    __shared__ float sh[12000];
    __shared__ float wmax[8];
    const int tid = threadIdx.x;

    if (blockIdx.x < 96) {
        const int b = blockIdx.x / 6, chunk = blockIdx.x % 6;
        float* md  = sh;
        float* mrd = sh + Tn;

        float lmax = -1e30f;
        for (int i = tid; i < Tn; i += 256) {
            float m = g_mag[b * Tn + i];
            float s = sel[b * Tn + i];
            md[i] = m; mrd[i] = s;
            lmax = fmaxf(lmax, m);
        }
        for (int o = 16; o > 0; o >>= 1)
            lmax = fmaxf(lmax, __shfl_down_sync(0xffffffffu, lmax, o));
        if ((tid & 31) == 0) wmax[tid >> 5] = lmax;
        __syncthreads();
        float maxm = wmax[0];
        #pragma unroll
        for (int w = 1; w < 8; w++) maxm = fmaxf(maxm, wmax[w]);
        for (int i = tid; i < Tn; i += 256) {
            float m = md[i], s = mrd[i];
            md[i]  = m * s;
            mrd[i] = (maxm - m) * s;
        }
        __syncthreads();

        const int i = chunk * 125 + tid;
        if (tid < 125) {
            float v1 = md[i], v2 = mrd[i];
            int r1 = 0, r2 = 0;
            #pragma unroll 5
            for (int j = 0; j < Tn; j++) {
                float u1 = md[j];
                r1 += (int)(u1 > v1) + (int)((u1 == v1) & (j < i));
                float u2 = mrd[j];
                r2 += (int)(u2 > v2) + (int)((u2 == v2) & (j < i));
            }
            if (r1 < KS) g_idx_act[b * KS + r1] = i;
            if (r2 < KS) g_idx_bkg[b * KS + r2] = i;
        }
    } else {
        const int w = tid >> 5, lane = tid & 31;
        const int pair = (blockIdx.x - 96) * 8 + w;   // 0..319
        const int b = pair / Cd, c = pair % Cd;
        unsigned* key = (unsigned*)(sh + w * 1500);
        float*    col = sh + w * 1500 + Tn;

        for (int i = lane; i < Tn; i += 32) {
            float v = g_cas[(b * Tn + i) * Cd + c];
            col[i] = v;
            unsigned u = __float_as_uint(v);
            key[i] = (u & 0x80000000u) ? ~u : (u | 0x80000000u);
        }
        __syncwarp();

        unsigned prefix = 0u;
        for (int bit = 31; bit >= 0; --bit) {
            unsigned cand = prefix | (1u << bit);
            int cnt = 0;
            for (int i = lane; i < Tn; i += 32) cnt += (int)(key[i] >= cand);
            cnt = (int)__reduce_add_sync(0xffffffffu, (unsigned)cnt);
            if (cnt >= KS) prefix = cand;
        }
        float thr;
        { unsigned u = prefix; u = (u & 0x80000000u) ? (u & 0x7fffffffu) : ~u;
          thr = __uint_as_float(u); }

        int cg = 0; float s = 0.f;
        for (int i = lane; i < Tn; i += 32)
            if (key[i] > prefix) { cg++; s += col[i]; }
        cg = (int)__reduce_add_sync(0xffffffffu, (unsigned)cg);
        for (int o = 16; o > 0; o >>= 1) s += __shfl_down_sync(0xffffffffu, s, o);
        if (lane == 0)
            g_sact[b * Cd + c] = (s + (float)(KS - cg) * thr) * (1.f / (float)KS);
    }
}

// ============================================================================
// K45: merged tail. grid 2992 x 256 threads.
// ============================================================================
__global__ void k45(const float4* __restrict__ x4, float* __restrict__ out)
{
    __shared__ float red[12 * Cd];
    __shared__ float sb[Cd], sa[Cd], eb[Cd], ea[Cd];
    const int tid = threadIdx.x;

    if (blockIdx.x < 2976) {
        int idx = blockIdx.x;
        int z = (idx >= 1488) ? 1 : 0;
        idx -= z * 1488;
        const int b = idx / KS, k = idx % KS;
        const int* I = z ? g_idx_bkg : g_idx_act;
        const int t = I[b * KS + k];
        const float4* s = x4 + (long)(b * Tn + t) * 1024;
        float4* d = (float4*)out + (z ? (OFF_FBKG / 4) : (OFF_FACT / 4))
                    + (long)(b * KS + k) * 1024;
        for (int i = tid; i < 1024; i += 256) d[i] = s[i];
    } else {
        const int b = blockIdx.x - 2976;
        float* score_act = out + OFF_SACT;
        float* score_bkg = out + OFF_SBKG;

        if (tid < 240) {
            int c = tid % Cd, p = tid / Cd;
            float s = 0.f;
            for (int k = p; k < KS; k += 12) {
                int t = g_idx_bkg[b * KS + k];
                s += g_cas[(b * Tn + t) * Cd + c];
            }
            red[p * Cd + c] = s;
        }
        __syncthreads();
        if (tid < Cd) {
            float s = 0.f;
            #pragma unroll
            for (int p = 0; p < 12; p++) s += red[p * Cd + tid];
            sb[tid] = s * (1.f / (float)KS);
            sa[tid] = g_sact[b * Cd + tid];
        }
        __syncthreads();
        if (tid < Cd) {
            float mb = -1e30f, ma = -1e30f;
            #pragma unroll
            for (int j = 0; j < Cd; j++) { mb = fmaxf(mb, sb[j]); ma = fmaxf(ma, sa[j]); }
            eb[tid] = expf(sb[tid] - mb);
            ea[tid] = expf(sa[tid] - ma);
        }
        __syncthreads();
        if (tid < Cd) {
            float Sb = 0.f, Sa = 0.f;
            #pragma unroll
            for (int j = 0; j < Cd; j++) { Sb += eb[j]; Sa += ea[j]; }
            score_bkg[b * Cd + tid] = eb[tid] / Sb;
            score_act[b * Cd + tid] = ea[tid] / Sa;
        }
    }
}

// ============================================================================
extern "C" void kernel_launch(void* const* d_in, const int* in_sizes, int n_in,
                              void* d_out, int out_size)
{
    const float* x    = (const float*)d_in[0];
    const float* W    = (const float*)d_in[1];
    const float* mask = (const float*)d_in[2];
    const float* sel  = (const float*)d_in[3];
    float* out = (float*)d_out;

    cudaFuncSetAttribute(k1_main, cudaFuncAttributeMaxDynamicSharedMemorySize, SM_TOTAL);

    k1_main<<<NROW / 16, 512, SM_TOTAL>>>(
        (const ulonglong2*)x, (const ulonglong2*)W, (const ulonglong2*)mask,
        (ulonglong2*)(out + OFF_FEAT), out + OFF_CSM);
    k23<<<136, 256>>>(sel);
    k45<<<2992, 256>>>((const float4*)x, out);
}

// round 9
// speedup vs baseline: 1.4600x; 1.1034x over previous
#include <cuda_runtime.h>
#include <math.h>

#define Bn   16
#define Tn   750
#define Fd   4096
#define Cd   20
#define KS   93
#define NROW (Bn*Tn)          // 12000

// ---- output layout (float elements) ----
#define OFF_SACT 0
#define OFF_SBKG 320
#define OFF_FACT 640
#define OFF_FBKG 6095488
#define OFF_FEAT 12190336
#define OFF_CSM  61342336

// ---- device scratch ----
__device__ float g_cas[NROW*Cd];
__device__ float g_mag[NROW];
__device__ int   g_idx_act[Bn*KS];
__device__ int   g_idx_bkg[Bn*KS];
__device__ float g_sact[Bn*Cd];

// ---- cp.async helpers ----
__device__ __forceinline__ unsigned smem_u32(const void* p) {
    return (unsigned)__cvta_generic_to_shared(p);
}
__device__ __forceinline__ void cp16(unsigned dst, const void* src) {
    asm volatile("cp.async.cg.shared.global [%0], [%1], 16;"
                 :: "r"(dst), "l"(src) : "memory");
}
#define CP_COMMIT() asm volatile("cp.async.commit_group;" ::: "memory")
#define CP_WAIT(n)  asm volatile("cp.async.wait_group %0;" :: "n"(n) : "memory")

// ============================================================================
// K1: fused per-row pass, cp.async-pipelined, 32 rows/block.
// 375 blocks x 512 threads (16 warps = 8 row-groups x 2 class-warps).
// Per warp: 4 rows x 10 classes, scalar fp32 accumulators (40 regs).
// Stage ring: 4 stages x (32 rows x 32 f4) for x and mask (128KB).
// W chunk [20][256] f4 (80KB). cass [32][20] (2.5KB). Total 215552B.
// ============================================================================
#define SM_OFF_W    0
#define SM_OFF_XS   81920
#define SM_OFF_MS   147456
#define SM_OFF_CASS 212992
#define SM_TOTAL    215552

__global__ __launch_bounds__(512, 1) void k1_main(
    const float4* __restrict__ xg, const float4* __restrict__ Wg,
    const float4* __restrict__ mg, float4* __restrict__ featg,
    float* __restrict__ cas_sm)
{
    extern __shared__ char sm[];
    float4* smw  = (float4*)(sm + SM_OFF_W);     // [Cd][256]
    float4* xs   = (float4*)(sm + SM_OFF_XS);    // [4][32][32]
    float4* msb  = (float4*)(sm + SM_OFF_MS);    // [4][32][32]
    float*  cass = (float*)(sm + SM_OFF_CASS);   // [32][Cd]

    const int tid  = threadIdx.x;
    const int lane = tid & 31;
    const int wrp  = tid >> 5;           // 0..15
    const int rg   = wrp >> 1;           // row-group 0..7  -> rows rg*4..rg*4+3
    const int cw   = wrp & 1;            // class-warp 0..1 -> classes cw*10..+9
    const int cbase = cw * 10;
    const int row0 = blockIdx.x * 32;

    // producer mapping: thread covers (row wrp, f4=lane) and (row wrp+16, f4=lane)
    const float4* xsrcA = xg + (size_t)(row0 + wrp)      * 1024 + lane;
    const float4* xsrcB = xg + (size_t)(row0 + wrp + 16) * 1024 + lane;
    const float4* msrcA = mg + (size_t)(row0 + wrp)      * 1024 + lane;
    const float4* msrcB = mg + (size_t)(row0 + wrp + 16) * 1024 + lane;
    const unsigned xsA = smem_u32(xs)  + (unsigned)((wrp)      * 32 + lane) * 16u;
    const unsigned xsB = smem_u32(xs)  + (unsigned)((wrp + 16) * 32 + lane) * 16u;
    const unsigned msA = smem_u32(msb) + (unsigned)((wrp)      * 32 + lane) * 16u;
    const unsigned msB = smem_u32(msb) + (unsigned)((wrp + 16) * 32 + lane) * 16u;

    float acc[10][4];
    #pragma unroll
    for (int c = 0; c < 10; c++)
        #pragma unroll
        for (int r = 0; r < 4; r++) acc[c][r] = 0.f;
    float ssqa = 0.f, ssqb = 0.f;

    // ---- pipeline prologue: stages 0..2 ----
    #pragma unroll
    for (int s = 0; s < 3; s++) {
        unsigned so = (unsigned)(s & 3) * 16384u;   // 1024 f4 * 16B per stage
        cp16(xsA + so, xsrcA + s * 32);
        cp16(xsB + so, xsrcB + s * 32);
        cp16(msA + so, msrcA + s * 32);
        cp16(msB + so, msrcB + s * 32);
        CP_COMMIT();
    }

    #define COMPUTE_SUB(s)                                                      \
    {                                                                           \
        const int stg = (s) & 3;                                                \
        const int wb  = ((s) & 7) * 32;                                         \
        /* feat writeout + ssq for this warp's two owned rows */                \
        float4 xa = xs[stg * 1024 + wrp * 32 + lane];                           \
        float4 xb = xs[stg * 1024 + (wrp + 16) * 32 + lane];                    \
        featg[(size_t)(row0 + wrp)      * 1024 + (s) * 32 + lane] = xa;         \
        featg[(size_t)(row0 + wrp + 16) * 1024 + (s) * 32 + lane] = xb;         \
        ssqa += xa.x*xa.x + xa.y*xa.y + xa.z*xa.z + xa.w*xa.w;                  \
        ssqb += xb.x*xb.x + xb.y*xb.y + xb.z*xb.z + xb.w*xb.w;                  \
        /* masked inputs for this warp's 4 compute rows */                      \
        float4 xm[4];                                                           \
        _Pragma("unroll")                                                       \
        for (int r = 0; r < 4; r++) {                                           \
            const int lrow = rg * 4 + r;                                        \
            float4 xv = xs[stg * 1024 + lrow * 32 + lane];                      \
            float4 mv = msb[stg * 1024 + lrow * 32 + lane];                     \
            xm[r].x = xv.x * mv.x; xm[r].y = xv.y * mv.y;                       \
            xm[r].z = xv.z * mv.z; xm[r].w = xv.w * mv.w;                       \
        }                                                                       \
        _Pragma("unroll")                                                       \
        for (int c = 0; c < 10; c++) {                                          \
            float4 wv = smw[(cbase + c) * 256 + wb + lane];                     \
            _Pragma("unroll")                                                   \
            for (int r = 0; r < 4; r++) {                                       \
                float a = acc[c][r];                                            \
                a = fmaf(wv.x, xm[r].x, a);                                     \
                a = fmaf(wv.y, xm[r].y, a);                                     \
                a = fmaf(wv.z, xm[r].z, a);                                     \
                a = fmaf(wv.w, xm[r].w, a);                                     \
                acc[c][r] = a;                                                  \
            }                                                                   \
        }                                                                       \
    }

    // ---- main loop over 32 sub-chunks ----
    for (int s = 0; s < 30; s++) {
        if ((s & 7) == 0) {              // new W chunk every 8 sub-chunks
            __syncthreads();
            const int ch = s >> 3;
            #pragma unroll
            for (int k = tid, it = 0; it < 10; it++, k += 512)
                smw[k] = __ldg(&Wg[(k >> 8) * 1024 + ch * 256 + (k & 255)]);
            __syncthreads();
        }
        CP_WAIT(2);
        __syncthreads();
        if (s + 3 < 32) {
            unsigned so = (unsigned)((s + 3) & 3) * 16384u;
            cp16(xsA + so, xsrcA + (s + 3) * 32);
            cp16(xsB + so, xsrcB + (s + 3) * 32);
            cp16(msA + so, msrcA + (s + 3) * 32);
            cp16(msB + so, msrcB + (s + 3) * 32);
            CP_COMMIT();
        }
        COMPUTE_SUB(s);
    }
    CP_WAIT(1); __syncthreads(); COMPUTE_SUB(30);
    CP_WAIT(0); __syncthreads(); COMPUTE_SUB(31);

    // ---- warp-local cas reduction (4 rows x 10 classes per warp) ----
    #pragma unroll
    for (int c = 0; c < 10; c++) {
        #pragma unroll
        for (int r = 0; r < 4; r++) {
            float s2 = acc[c][r];
            s2 += __shfl_down_sync(0xffffffffu, s2, 16);
            s2 += __shfl_down_sync(0xffffffffu, s2, 8);
            s2 += __shfl_down_sync(0xffffffffu, s2, 4);
            s2 += __shfl_down_sync(0xffffffffu, s2, 2);
            s2 += __shfl_down_sync(0xffffffffu, s2, 1);
            if (lane == 0) {
                int cc = cbase + c;
                int lrow = rg * 4 + r;
                cass[lrow * Cd + cc] = s2;
                g_cas[(row0 + lrow) * Cd + cc] = s2;
            }
        }
    }
    // ---- mag: warp owns rows wrp and wrp+16 (fp64 cross-lane reduce) ----
    {
        double da = (double)ssqa, db = (double)ssqb;
        #pragma unroll
        for (int o = 16; o > 0; o >>= 1) {
            da += __shfl_down_sync(0xffffffffu, da, o);
            db += __shfl_down_sync(0xffffffffu, db, o);
        }
        if (lane == 0) {
            g_mag[row0 + wrp]      = (float)sqrt(da);
            g_mag[row0 + wrp + 16] = (float)sqrt(db);
        }
    }
    __syncthreads();

    // ---- cas softmax over classes, one thread per row ----
    if (tid < 32) {
        int row = row0 + tid;
        float m = -1e30f;
        #pragma unroll
        for (int c = 0; c < Cd; c++) m = fmaxf(m, cass[tid * Cd + c]);
        float e[Cd]; float s = 0.f;
        #pragma unroll
        for (int c = 0; c < Cd; c++) { e[c] = expf(cass[tid * Cd + c] - m); s += e[c]; }
        float inv = 1.f / s;
        #pragma unroll
        for (int c = 0; c < Cd; c++) cas_sm[row * Cd + c] = e[c] * inv;
    }
}

// ============================================================================
// K23: merged top-k kernels. grid 136 x 256 threads.
// ============================================================================
__global__ void k23(const float* __restrict__ sel)
{
    __shared__ float sh[12000];
    __shared__ float wmax[8];
    const int tid = threadIdx.x;

    if (blockIdx.x < 96) {
        const int b = blockIdx.x / 6, chunk = blockIdx.x % 6;
        float* md  = sh;
        float* mrd = sh + Tn;

        float lmax = -1e30f;
        for (int i = tid; i < Tn; i += 256) {
            float m = g_mag[b * Tn + i];
            float s = sel[b * Tn + i];
            md[i] = m; mrd[i] = s;
            lmax = fmaxf(lmax, m);
        }
        for (int o = 16; o > 0; o >>= 1)
            lmax = fmaxf(lmax, __shfl_down_sync(0xffffffffu, lmax, o));
        if ((tid & 31) == 0) wmax[tid >> 5] = lmax;
        __syncthreads();
        float maxm = wmax[0];
        #pragma unroll
        for (int w = 1; w < 8; w++) maxm = fmaxf(maxm, wmax[w]);
        for (int i = tid; i < Tn; i += 256) {
            float m = md[i], s = mrd[i];
            md[i]  = m * s;
            mrd[i] = (maxm - m) * s;
        }
        __syncthreads();

        const int i = chunk * 125 + tid;
        if (tid < 125) {
            float v1 = md[i], v2 = mrd[i];
            int r1 = 0, r2 = 0;
            #pragma unroll 5
            for (int j = 0; j < Tn; j++) {
                float u1 = md[j];
                r1 += (int)(u1 > v1) + (int)((u1 == v1) & (j < i));
                float u2 = mrd[j];
                r2 += (int)(u2 > v2) + (int)((u2 == v2) & (j < i));
            }
            if (r1 < KS) g_idx_act[b * KS + r1] = i;
            if (r2 < KS) g_idx_bkg[b * KS + r2] = i;
        }
    } else {
        const int w = tid >> 5, lane = tid & 31;
        const int pair = (blockIdx.x - 96) * 8 + w;   // 0..319
        const int b = pair / Cd, c = pair % Cd;
        unsigned* key = (unsigned*)(sh + w * 1500);
        float*    col = sh + w * 1500 + Tn;

        for (int i = lane; i < Tn; i += 32) {
            float v = g_cas[(b * Tn + i) * Cd + c];
            col[i] = v;
            unsigned u = __float_as_uint(v);
            key[i] = (u & 0x80000000u) ? ~u : (u | 0x80000000u);
        }
        __syncwarp();

        unsigned prefix = 0u;
        for (int bit = 31; bit >= 0; --bit) {
            unsigned cand = prefix | (1u << bit);
            int cnt = 0;
            for (int i = lane; i < Tn; i += 32) cnt += (int)(key[i] >= cand);
            cnt = (int)__reduce_add_sync(0xffffffffu, (unsigned)cnt);
            if (cnt >= KS) prefix = cand;
        }
        float thr;
        { unsigned u = prefix; u = (u & 0x80000000u) ? (u & 0x7fffffffu) : ~u;
          thr = __uint_as_float(u); }

        int cg = 0; float s = 0.f;
        for (int i = lane; i < Tn; i += 32)
            if (key[i] > prefix) { cg++; s += col[i]; }
        cg = (int)__reduce_add_sync(0xffffffffu, (unsigned)cg);
        for (int o = 16; o > 0; o >>= 1) s += __shfl_down_sync(0xffffffffu, s, o);
        if (lane == 0)
            g_sact[b * Cd + c] = (s + (float)(KS - cg) * thr) * (1.f / (float)KS);
    }
}

// ============================================================================
// K45: merged tail. grid 2992 x 256 threads.
// ============================================================================
__global__ void k45(const float4* __restrict__ x4, float* __restrict__ out)
{
    __shared__ float red[12 * Cd];
    __shared__ float sb[Cd], sa[Cd], eb[Cd], ea[Cd];
    const int tid = threadIdx.x;

    if (blockIdx.x < 2976) {
        int idx = blockIdx.x;
        int z = (idx >= 1488) ? 1 : 0;
        idx -= z * 1488;
        const int b = idx / KS, k = idx % KS;
        const int* I = z ? g_idx_bkg : g_idx_act;
        const int t = I[b * KS + k];
        const float4* s = x4 + (long)(b * Tn + t) * 1024;
        float4* d = (float4*)out + (z ? (OFF_FBKG / 4) : (OFF_FACT / 4))
                    + (long)(b * KS + k) * 1024;
        for (int i = tid; i < 1024; i += 256) d[i] = s[i];
    } else {
        const int b = blockIdx.x - 2976;
        float* score_act = out + OFF_SACT;
        float* score_bkg = out + OFF_SBKG;

        if (tid < 240) {
            int c = tid % Cd, p = tid / Cd;
            float s = 0.f;
            for (int k = p; k < KS; k += 12) {
                int t = g_idx_bkg[b * KS + k];
                s += g_cas[(b * Tn + t) * Cd + c];
            }
            red[p * Cd + c] = s;
        }
        __syncthreads();
        if (tid < Cd) {
            float s = 0.f;
            #pragma unroll
            for (int p = 0; p < 12; p++) s += red[p * Cd + tid];
            sb[tid] = s * (1.f / (float)KS);
            sa[tid] = g_sact[b * Cd + tid];
        }
        __syncthreads();
        if (tid < Cd) {
            float mb = -1e30f, ma = -1e30f;
            #pragma unroll
            for (int j = 0; j < Cd; j++) { mb = fmaxf(mb, sb[j]); ma = fmaxf(ma, sa[j]); }
            eb[tid] = expf(sb[tid] - mb);
            ea[tid] = expf(sa[tid] - ma);
        }
        __syncthreads();
        if (tid < Cd) {
            float Sb = 0.f, Sa = 0.f;
            #pragma unroll
            for (int j = 0; j < Cd; j++) { Sb += eb[j]; Sa += ea[j]; }
            score_bkg[b * Cd + tid] = eb[tid] / Sb;
            score_act[b * Cd + tid] = ea[tid] / Sa;
        }
    }
}

// ============================================================================
extern "C" void kernel_launch(void* const* d_in, const int* in_sizes, int n_in,
                              void* d_out, int out_size)
{
    const float* x    = (const float*)d_in[0];
    const float* W    = (const float*)d_in[1];
    const float* mask = (const float*)d_in[2];
    const float* sel  = (const float*)d_in[3];
    float* out = (float*)d_out;

    cudaFuncSetAttribute(k1_main, cudaFuncAttributeMaxDynamicSharedMemorySize, SM_TOTAL);

    k1_main<<<NROW / 32, 512, SM_TOTAL>>>(
        (const float4*)x, (const float4*)W, (const float4*)mask,
        (float4*)(out + OFF_FEAT), out + OFF_CSM);
    k23<<<136, 256>>>(sel);
    k45<<<2992, 256>>>((const float4*)x, out);
}

// round 10
// speedup vs baseline: 1.6959x; 1.1616x over previous
#include <cuda_runtime.h>
#include <math.h>

#define Bn   16
#define Tn   750
#define Fd   4096
#define Cd   20
#define KS   93
#define NROW (Bn*Tn)          // 12000

// ---- output layout (float elements) ----
#define OFF_SACT 0
#define OFF_SBKG 320
#define OFF_FACT 640
#define OFF_FBKG 6095488
#define OFF_FEAT 12190336
#define OFF_CSM  61342336

// ---- device scratch ----
__device__ float g_cas[NROW*Cd];
__device__ float g_mag[NROW];
__device__ int   g_idx_act[Bn*KS];
__device__ int   g_idx_bkg[Bn*KS];
__device__ float g_sact[Bn*Cd];

// ---- cp.async helpers ----
__device__ __forceinline__ unsigned smem_u32(const void* p) {
    return (unsigned)__cvta_generic_to_shared(p);
}
__device__ __forceinline__ void cp16(unsigned dst, const void* src) {
    asm volatile("cp.async.cg.shared.global [%0], [%1], 16;"
                 :: "r"(dst), "l"(src) : "memory");
}
#define CP_COMMIT() asm volatile("cp.async.commit_group;" ::: "memory")
#define CP_WAIT(n)  asm volatile("cp.async.wait_group %0;" :: "n"(n) : "memory")

// ============================================================================
// K1: fused per-row pass, cp.async-pipelined, 16 rows/block, 2 blocks/SM.
// 750 blocks x 256 threads (8 warps = 4 row-groups x 2 class-warps).
// Per warp: 4 rows x 10 classes, scalar fp32 accumulators.
// Stage ring: 4 stages x (16 rows x 32 f4) for x and mask (64KB).
// W chunk [20][128] f4 (40KB, 8 chunks). cass [16][20] (1.28KB).
// smem total 107776B -> two co-resident blocks per SM hide barrier bubbles.
// ============================================================================
#define SM_OFF_W    0
#define SM_OFF_XS   40960
#define SM_OFF_MS   73728
#define SM_OFF_CASS 106496
#define SM_TOTAL    107776

__global__ __launch_bounds__(256, 2) void k1_main(
    const float4* __restrict__ xg, const float4* __restrict__ Wg,
    const float4* __restrict__ mg, float4* __restrict__ featg,
    float* __restrict__ cas_sm)
{
    extern __shared__ char sm[];
    float4* smw  = (float4*)(sm + SM_OFF_W);     // [Cd][128]
    float4* xs   = (float4*)(sm + SM_OFF_XS);    // [4][16][32]
    float4* msb  = (float4*)(sm + SM_OFF_MS);    // [4][16][32]
    float*  cass = (float*)(sm + SM_OFF_CASS);   // [16][Cd]

    const int tid  = threadIdx.x;
    const int lane = tid & 31;
    const int wrp  = tid >> 5;           // 0..7
    const int rg   = wrp >> 1;           // row-group 0..3 -> rows rg*4..rg*4+3
    const int cw   = wrp & 1;            // class-warp 0..1 -> classes cw*10..+9
    const int cbase = cw * 10;
    const int row0 = blockIdx.x * 16;

    // producer mapping: thread covers (row wrp, f4=lane) and (row wrp+8, f4=lane)
    const float4* xsrcA = xg + (size_t)(row0 + wrp)     * 1024 + lane;
    const float4* xsrcB = xg + (size_t)(row0 + wrp + 8) * 1024 + lane;
    const float4* msrcA = mg + (size_t)(row0 + wrp)     * 1024 + lane;
    const float4* msrcB = mg + (size_t)(row0 + wrp + 8) * 1024 + lane;
    const unsigned xsA = smem_u32(xs)  + (unsigned)((wrp)     * 32 + lane) * 16u;
    const unsigned xsB = smem_u32(xs)  + (unsigned)((wrp + 8) * 32 + lane) * 16u;
    const unsigned msA = smem_u32(msb) + (unsigned)((wrp)     * 32 + lane) * 16u;
    const unsigned msB = smem_u32(msb) + (unsigned)((wrp + 8) * 32 + lane) * 16u;

    float acc[10][4];
    #pragma unroll
    for (int c = 0; c < 10; c++)
        #pragma unroll
        for (int r = 0; r < 4; r++) acc[c][r] = 0.f;
    float ssqa = 0.f, ssqb = 0.f;

    // ---- pipeline prologue: stages 0..2 ----
    #pragma unroll
    for (int s = 0; s < 3; s++) {
        unsigned so = (unsigned)(s & 3) * 8192u;   // 512 f4 * 16B per stage
        cp16(xsA + so, xsrcA + s * 32);
        cp16(xsB + so, xsrcB + s * 32);
        cp16(msA + so, msrcA + s * 32);
        cp16(msB + so, msrcB + s * 32);
        CP_COMMIT();
    }

    #define COMPUTE_SUB(s)                                                      \
    {                                                                           \
        const int stg = (s) & 3;                                                \
        const int wb  = ((s) & 3) * 32;                                         \
        /* feat writeout + ssq for this warp's two owned rows */                \
        float4 xa = xs[stg * 512 + wrp * 32 + lane];                            \
        float4 xb = xs[stg * 512 + (wrp + 8) * 32 + lane];                      \
        featg[(size_t)(row0 + wrp)     * 1024 + (s) * 32 + lane] = xa;          \
        featg[(size_t)(row0 + wrp + 8) * 1024 + (s) * 32 + lane] = xb;          \
        ssqa += xa.x*xa.x + xa.y*xa.y + xa.z*xa.z + xa.w*xa.w;                  \
        ssqb += xb.x*xb.x + xb.y*xb.y + xb.z*xb.z + xb.w*xb.w;                  \
        /* masked inputs for this warp's 4 compute rows */                      \
        float4 xm[4];                                                           \
        _Pragma("unroll")                                                       \
        for (int r = 0; r < 4; r++) {                                           \
            const int lrow = rg * 4 + r;                                        \
            float4 xv = xs[stg * 512 + lrow * 32 + lane];                       \
            float4 mv = msb[stg * 512 + lrow * 32 + lane];                      \
            xm[r].x = xv.x * mv.x; xm[r].y = xv.y * mv.y;                       \
            xm[r].z = xv.z * mv.z; xm[r].w = xv.w * mv.w;                       \
        }                                                                       \
        _Pragma("unroll")                                                       \
        for (int c = 0; c < 10; c++) {                                          \
            float4 wv = smw[(cbase + c) * 128 + wb + lane];                     \
            _Pragma("unroll")                                                   \
            for (int r = 0; r < 4; r++) {                                       \
                float a = acc[c][r];                                            \
                a = fmaf(wv.x, xm[r].x, a);                                     \
                a = fmaf(wv.y, xm[r].y, a);                                     \
                a = fmaf(wv.z, xm[r].z, a);                                     \
                a = fmaf(wv.w, xm[r].w, a);                                     \
                acc[c][r] = a;                                                  \
            }                                                                   \
        }                                                                       \
    }

    // ---- main loop over 32 sub-chunks ----
    for (int s = 0; s < 30; s++) {
        if ((s & 3) == 0) {              // new W chunk every 4 sub-chunks
            __syncthreads();
            const int ch = s >> 2;
            #pragma unroll
            for (int k = tid, it = 0; it < 10; it++, k += 256)
                smw[k] = __ldg(&Wg[(k >> 7) * 1024 + ch * 128 + (k & 127)]);
            __syncthreads();
        }
        CP_WAIT(2);
        __syncthreads();
        if (s + 3 < 32) {
            unsigned so = (unsigned)((s + 3) & 3) * 8192u;
            cp16(xsA + so, xsrcA + (s + 3) * 32);
            cp16(xsB + so, xsrcB + (s + 3) * 32);
            cp16(msA + so, msrcA + (s + 3) * 32);
            cp16(msB + so, msrcB + (s + 3) * 32);
            CP_COMMIT();
        }
        COMPUTE_SUB(s);
    }
    CP_WAIT(1); __syncthreads(); COMPUTE_SUB(30);
    CP_WAIT(0); __syncthreads(); COMPUTE_SUB(31);

    // ---- warp-local cas reduction (4 rows x 10 classes per warp) ----
    #pragma unroll
    for (int c = 0; c < 10; c++) {
        #pragma unroll
        for (int r = 0; r < 4; r++) {
            float s2 = acc[c][r];
            s2 += __shfl_down_sync(0xffffffffu, s2, 16);
            s2 += __shfl_down_sync(0xffffffffu, s2, 8);
            s2 += __shfl_down_sync(0xffffffffu, s2, 4);
            s2 += __shfl_down_sync(0xffffffffu, s2, 2);
            s2 += __shfl_down_sync(0xffffffffu, s2, 1);
            if (lane == 0) {
                int cc = cbase + c;
                int lrow = rg * 4 + r;
                cass[lrow * Cd + cc] = s2;
                g_cas[(row0 + lrow) * Cd + cc] = s2;
            }
        }
    }
    // ---- mag: warp owns rows wrp and wrp+8 (fp64 cross-lane reduce) ----
    {
        double da = (double)ssqa, db = (double)ssqb;
        #pragma unroll
        for (int o = 16; o > 0; o >>= 1) {
            da += __shfl_down_sync(0xffffffffu, da, o);
            db += __shfl_down_sync(0xffffffffu, db, o);
        }
        if (lane == 0) {
            g_mag[row0 + wrp]     = (float)sqrt(da);
            g_mag[row0 + wrp + 8] = (float)sqrt(db);
        }
    }
    __syncthreads();

    // ---- cas softmax over classes, one thread per row ----
    if (tid < 16) {
        int row = row0 + tid;
        float m = -1e30f;
        #pragma unroll
        for (int c = 0; c < Cd; c++) m = fmaxf(m, cass[tid * Cd + c]);
        float e[Cd]; float s = 0.f;
        #pragma unroll
        for (int c = 0; c < Cd; c++) { e[c] = expf(cass[tid * Cd + c] - m); s += e[c]; }
        float inv = 1.f / s;
        #pragma unroll
        for (int c = 0; c < Cd; c++) cas_sm[row * Cd + c] = e[c] * inv;
    }
}

// ============================================================================
// K23: merged top-k kernels. grid 136 x 256 threads.
// ============================================================================
__global__ void k23(const float* __restrict__ sel)
{
    __shared__ float sh[12000];
    __shared__ float wmax[8];
    const int tid = threadIdx.x;

    if (blockIdx.x < 96) {
        const int b = blockIdx.x / 6, chunk = blockIdx.x % 6;
        float* md  = sh;
        float* mrd = sh + Tn;

        float lmax = -1e30f;
        for (int i = tid; i < Tn; i += 256) {
            float m = g_mag[b * Tn + i];
            float s = sel[b * Tn + i];
            md[i] = m; mrd[i] = s;
            lmax = fmaxf(lmax, m);
        }
        for (int o = 16; o > 0; o >>= 1)
            lmax = fmaxf(lmax, __shfl_down_sync(0xffffffffu, lmax, o));
        if ((tid & 31) == 0) wmax[tid >> 5] = lmax;
        __syncthreads();
        float maxm = wmax[0];
        #pragma unroll
        for (int w = 1; w < 8; w++) maxm = fmaxf(maxm, wmax[w]);
        for (int i = tid; i < Tn; i += 256) {
            float m = md[i], s = mrd[i];
            md[i]  = m * s;
            mrd[i] = (maxm - m) * s;
        }
        __syncthreads();

        const int i = chunk * 125 + tid;
        if (tid < 125) {
            float v1 = md[i], v2 = mrd[i];
            int r1 = 0, r2 = 0;
            #pragma unroll 5
            for (int j = 0; j < Tn; j++) {
                float u1 = md[j];
                r1 += (int)(u1 > v1) + (int)((u1 == v1) & (j < i));
                float u2 = mrd[j];
                r2 += (int)(u2 > v2) + (int)((u2 == v2) & (j < i));
            }
            if (r1 < KS) g_idx_act[b * KS + r1] = i;
            if (r2 < KS) g_idx_bkg[b * KS + r2] = i;
        }
    } else {
        const int w = tid >> 5, lane = tid & 31;
        const int pair = (blockIdx.x - 96) * 8 + w;   // 0..319
        const int b = pair / Cd, c = pair % Cd;
        unsigned* key = (unsigned*)(sh + w * 1500);
        float*    col = sh + w * 1500 + Tn;

        for (int i = lane; i < Tn; i += 32) {
            float v = g_cas[(b * Tn + i) * Cd + c];
            col[i] = v;
            unsigned u = __float_as_uint(v);
            key[i] = (u & 0x80000000u) ? ~u : (u | 0x80000000u);
        }
        __syncwarp();

        unsigned prefix = 0u;
        for (int bit = 31; bit >= 0; --bit) {
            unsigned cand = prefix | (1u << bit);
            int cnt = 0;
            for (int i = lane; i < Tn; i += 32) cnt += (int)(key[i] >= cand);
            cnt = (int)__reduce_add_sync(0xffffffffu, (unsigned)cnt);
            if (cnt >= KS) prefix = cand;
        }
        float thr;
        { unsigned u = prefix; u = (u & 0x80000000u) ? (u & 0x7fffffffu) : ~u;
          thr = __uint_as_float(u); }

        int cg = 0; float s = 0.f;
        for (int i = lane; i < Tn; i += 32)
            if (key[i] > prefix) { cg++; s += col[i]; }
        cg = (int)__reduce_add_sync(0xffffffffu, (unsigned)cg);
        for (int o = 16; o > 0; o >>= 1) s += __shfl_down_sync(0xffffffffu, s, o);
        if (lane == 0)
            g_sact[b * Cd + c] = (s + (float)(KS - cg) * thr) * (1.f / (float)KS);
    }
}

// ============================================================================
// K45: merged tail. grid 2992 x 256 threads.
// ============================================================================
__global__ void k45(const float4* __restrict__ x4, float* __restrict__ out)
{
    __shared__ float red[12 * Cd];
    __shared__ float sb[Cd], sa[Cd], eb[Cd], ea[Cd];
    const int tid = threadIdx.x;

    if (blockIdx.x < 2976) {
        int idx = blockIdx.x;
        int z = (idx >= 1488) ? 1 : 0;
        idx -= z * 1488;
        const int b = idx / KS, k = idx % KS;
        const int* I = z ? g_idx_bkg : g_idx_act;
        const int t = I[b * KS + k];
        const float4* s = x4 + (long)(b * Tn + t) * 1024;
        float4* d = (float4*)out + (z ? (OFF_FBKG / 4) : (OFF_FACT / 4))
                    + (long)(b * KS + k) * 1024;
        for (int i = tid; i < 1024; i += 256) d[i] = s[i];
    } else {
        const int b = blockIdx.x - 2976;
        float* score_act = out + OFF_SACT;
        float* score_bkg = out + OFF_SBKG;

        if (tid < 240) {
            int c = tid % Cd, p = tid / Cd;
            float s = 0.f;
            for (int k = p; k < KS; k += 12) {
                int t = g_idx_bkg[b * KS + k];
                s += g_cas[(b * Tn + t) * Cd + c];
            }
            red[p * Cd + c] = s;
        }
        __syncthreads();
        if (tid < Cd) {
            float s = 0.f;
            #pragma unroll
            for (int p = 0; p < 12; p++) s += red[p * Cd + tid];
            sb[tid] = s * (1.f / (float)KS);
            sa[tid] = g_sact[b * Cd + tid];
        }
        __syncthreads();
        if (tid < Cd) {
            float mb = -1e30f, ma = -1e30f;
            #pragma unroll
            for (int j = 0; j < Cd; j++) { mb = fmaxf(mb, sb[j]); ma = fmaxf(ma, sa[j]); }
            eb[tid] = expf(sb[tid] - mb);
            ea[tid] = expf(sa[tid] - ma);
        }
        __syncthreads();
        if (tid < Cd) {
            float Sb = 0.f, Sa = 0.f;
            #pragma unroll
            for (int j = 0; j < Cd; j++) { Sb += eb[j]; Sa += ea[j]; }
            score_bkg[b * Cd + tid] = eb[tid] / Sb;
            score_act[b * Cd + tid] = ea[tid] / Sa;
        }
    }
}

// ============================================================================
extern "C" void kernel_launch(void* const* d_in, const int* in_sizes, int n_in,
                              void* d_out, int out_size)
{
    const float* x    = (const float*)d_in[0];
    const float* W    = (const float*)d_in[1];
    const float* mask = (const float*)d_in[2];
    const float* sel  = (const float*)d_in[3];
    float* out = (float*)d_out;

    cudaFuncSetAttribute(k1_main, cudaFuncAttributeMaxDynamicSharedMemorySize, SM_TOTAL);

    k1_main<<<NROW / 16, 256, SM_TOTAL>>>(
        (const float4*)x, (const float4*)W, (const float4*)mask,
        (float4*)(out + OFF_FEAT), out + OFF_CSM);
    k23<<<136, 256>>>(sel);
    k45<<<2992, 256>>>((const float4*)x, out);
}